// round 13
// baseline (speedup 1.0000x reference)
#include <cuda_runtime.h>
#include <cuda_fp16.h>
#include <cstdint>

// ---------------- problem constants ----------------
#define T_TOK   8192
#define DMODEL  1024
#define DFF     4096
#define NEXP    8
#define ECAP    4096
#define NSLOTS  (NEXP * ECAP)                  // 32768
#define MAXTILES 160

// ---------------- device scratch (static; no allocation) ----------------
__device__ __align__(16) __half    g_hh[(size_t)NSLOTS * DFF];        // 256 MiB h (fp16)
__device__ __align__(16) float     g_y[(size_t)NSLOTS * DMODEL];      // 128 MiB
__device__ __align__(16) __half    g_xh[(size_t)T_TOK * DMODEL];      // 16 MiB
// packed half2 weights: [e][kp][n], uint = (half lo = k=2kp, half hi = k=2kp+1)
__device__ __align__(16) unsigned  g_w1h[(size_t)NEXP * (DMODEL / 2) * DFF];  // 64 MiB
__device__ __align__(16) unsigned  g_w2h[(size_t)NEXP * (DFF / 2) * DMODEL];  // 64 MiB
__device__ int   g_tok[NSLOTS];
__device__ int   g_s0[T_TOK], g_s1[T_TOK];
__device__ float g_w0[T_TOK], g_w1w[T_TOK];
__device__ int   g_fill[NEXP];
__device__ int   g_ntiles;
__device__ int   g_tile_e[MAXTILES], g_tile_start[MAXTILES], g_tile_cnt[MAXTILES];

// ---------------- helpers ----------------
__device__ __forceinline__ uint32_t smem_u32(const void* p) {
    uint32_t a;
    asm("{ .reg .u64 t; cvta.to.shared.u64 t, %1; cvt.u32.u64 %0, t; }" : "=r"(a) : "l"(p));
    return a;
}
__device__ __forceinline__ void cp16(uint32_t dst, const void* src) {
    asm volatile("cp.async.cg.shared.global [%0], [%1], 16;" :: "r"(dst), "l"(src));
}
__device__ __forceinline__ void cp_commit() {
    asm volatile("cp.async.commit_group;" ::: "memory");
}
__device__ __forceinline__ void cp_wait1() {
    asm volatile("cp.async.wait_group 1;" ::: "memory");
}
__device__ __forceinline__ uint32_t ldsu(uint32_t addr) {
    uint32_t v;
    asm volatile("ld.shared.b32 %0, [%1];" : "=r"(v) : "r"(addr));
    return v;
}
__device__ __forceinline__ void ldm4(uint32_t addr, uint32_t* r) {
    asm volatile("ldmatrix.sync.aligned.m8n8.x4.shared.b16 {%0,%1,%2,%3}, [%4];"
        : "=r"(r[0]), "=r"(r[1]), "=r"(r[2]), "=r"(r[3]) : "r"(addr));
}
__device__ __forceinline__ unsigned pack2(float lo, float hi) {
    __half2 h = __floats2half2_rn(lo, hi);
    return *reinterpret_cast<unsigned*>(&h);
}
__device__ __forceinline__ void mma_f16(float* d, const uint32_t* a, const uint32_t* b) {
    asm volatile(
        "mma.sync.aligned.m16n8k16.row.col.f32.f16.f16.f32 "
        "{%0,%1,%2,%3}, {%4,%5,%6,%7}, {%8,%9}, {%0,%1,%2,%3};\n"
        : "+f"(d[0]), "+f"(d[1]), "+f"(d[2]), "+f"(d[3])
        : "r"(a[0]), "r"(a[1]), "r"(a[2]), "r"(a[3]),
          "r"(b[0]), "r"(b[1]));
}

// ---- launch 0: convert w1/w2 -> k-pair-interleaved half2 (+ zero counters) ----
#define W_UINTS ((size_t)NEXP * (DMODEL / 2) * DFF)
__global__ void convert_w(const float* __restrict__ w1, const float* __restrict__ w2) {
    if (blockIdx.x == 0 && threadIdx.x < NEXP) g_fill[threadIdx.x] = 0;
    size_t i = (size_t)blockIdx.x * blockDim.x + threadIdx.x;
    if (i < W_UINTS) {
        size_t row = i / DFF, n = i % DFF;
        size_t e = row / (DMODEL / 2), kp = row % (DMODEL / 2);
        size_t base = (e * DMODEL + 2 * kp) * DFF + n;
        g_w1h[i] = pack2(w1[base], w1[base + DFF]);
    } else if (i < 2 * W_UINTS) {
        size_t j = i - W_UINTS;
        size_t row = j / DMODEL, n = j % DMODEL;
        size_t e = row / (DFF / 2), kp = row % (DFF / 2);
        size_t base = (e * DFF + 2 * kp) * DMODEL + n;
        g_w2h[j] = pack2(w2[base], w2[base + DMODEL]);
    }
}

// ---- launch 1: gate + fp16(x) + direct slot assignment ----
__global__ void gate_kernel(const float* __restrict__ x, const float* __restrict__ gumbel,
                            const float* __restrict__ gw, const float* __restrict__ gb) {
    int t = (blockIdx.x * blockDim.x + threadIdx.x) >> 5;
    int lane = threadIdx.x & 31;
    if (t >= T_TOK) return;
    const float* xr = x + (size_t)t * DMODEL;
    unsigned* xo = reinterpret_cast<unsigned*>(g_xh + (size_t)t * DMODEL);
    float acc[NEXP];
#pragma unroll
    for (int e = 0; e < NEXP; e++) acc[e] = 0.f;
    for (int d = lane * 4; d < DMODEL; d += 128) {
        float4 xv = *reinterpret_cast<const float4*>(xr + d);
        uint2 hv;
        hv.x = pack2(xv.x, xv.y);
        hv.y = pack2(xv.z, xv.w);
        *reinterpret_cast<uint2*>(xo + d / 2) = hv;
        float xs[4] = {xv.x, xv.y, xv.z, xv.w};
        const float* g0 = gw + (size_t)d * NEXP;
#pragma unroll
        for (int j = 0; j < 4; j++)
#pragma unroll
            for (int e = 0; e < NEXP; e++) acc[e] += xs[j] * g0[j * NEXP + e];
    }
#pragma unroll
    for (int e = 0; e < NEXP; e++)
#pragma unroll
        for (int off = 16; off; off >>= 1)
            acc[e] += __shfl_xor_sync(0xffffffffu, acc[e], off);
    if (lane == 0) {
        float v[NEXP];
#pragma unroll
        for (int e = 0; e < NEXP; e++) v[e] = acc[e] + gb[e] + gumbel[t * NEXP + e];
        int b0 = 0; float m0 = v[0];
#pragma unroll
        for (int e = 1; e < NEXP; e++) if (v[e] > m0) { m0 = v[e]; b0 = e; }
        int b1 = -1; float m1 = -3.4e38f;
#pragma unroll
        for (int e = 0; e < NEXP; e++) {
            if (e == b0) continue;
            if (v[e] > m1) { m1 = v[e]; b1 = e; }
        }
        float e1v = expf(m1 - m0);
        float inv = 1.f / (1.f + e1v);
        g_w0[t] = inv; g_w1w[t] = e1v * inv;
        int s0 = b0 * ECAP + atomicAdd(&g_fill[b0], 1);
        g_tok[s0] = t; g_s0[t] = s0;
        int s1 = b1 * ECAP + atomicAdd(&g_fill[b1], 1);
        g_tok[s1] = t; g_s1[t] = s1;
    }
}

// ---- launch 2: build m-tile map ----
__global__ void tilemap_kernel() {
    if (threadIdx.x == 0) {
        int nt = 0;
        for (int e = 0; e < NEXP; e++) {
            int c = g_fill[e];
            if (c > ECAP) c = ECAP;
            int base = e * ECAP;
            for (int s = 0; s < c; s += 128) {
                g_tile_e[nt] = e;
                g_tile_start[nt] = base + s;
                g_tile_cnt[nt] = (c - s < 128) ? (c - s) : 128;
                nt++;
            }
        }
        g_ntiles = nt;
    }
}

// ---------------- grouped GEMM, fp16 m16n8k16, 3 CTAs/SM ----------------
// BM=128 BN=64 BK=64(half), 4 warps (2x2 grid, warp tile 64x32), cp.async 3-stage.
// A stage: 128 rows x 128B, unit swizzle g^(r&7)   -> conflict-free (+ ldmatrix).
// B stage: 32 kp-rows x 288B (72 words, 72%32==8)  -> conflict-free scalar LDS.
// 3 stages x 25600B = 76800B dyn smem; with 1KB driver reserve -> exactly 3 CTAs/SM.
#define SM_A_BYTES 16384
#define SM_B_STRIDE 288
#define STAGE_BYTES (SM_A_BYTES + 32 * SM_B_STRIDE)   // 25600
#define NSTAGE 3
#define SMEM_TOT (NSTAGE * STAGE_BYTES)                // 76800

template <bool GATHER, bool RELU>
__global__ void __launch_bounds__(128, 3)
gemm_fp16(const __half* __restrict__ Aext, int lda,
          const unsigned* __restrict__ B, long estrideU, int N,
          const float* __restrict__ bias, int Ksize) {
    extern __shared__ char smem[];
    int tix = blockIdx.y;
    if (tix >= g_ntiles) return;
    int e = g_tile_e[tix];
    int slot0 = g_tile_start[tix];
    int mc = g_tile_cnt[tix];
    int n0 = blockIdx.x * 64;

    uint32_t sm = smem_u32(smem);
    int tid = threadIdx.x;
    int lane = tid & 31, wid = tid >> 5;
    int wm = wid >> 1, wn = wid & 1;          // 2x2 warps, 64x32 each
    int gid = lane >> 2, tig = lane & 3;

    const __half* Abase = GATHER ? Aext : g_hh;
    const float* biasE = bias + (size_t)e * N;

    // ---- A staging map: rows r0+16i, unit kg (swizzled) ----
    int r0 = tid >> 3, kg = tid & 7;
    uint32_t aD0 = (uint32_t)r0 * 128u + 16u * (uint32_t)(kg ^ (r0 & 7));
    uint32_t arow[8];
#pragma unroll
    for (int i = 0; i < 8; i++) {
        int row = i * 16 + r0;
        int rc = row < mc ? row : (mc - 1);
        int rr = GATHER ? g_tok[slot0 + rc] : (slot0 + rc);
        arow[i] = (uint32_t)rr * (uint32_t)lda;   // in halves
    }
    const __half* Ab = Abase + kg * 8;

    // ---- B staging map: rows kp0+8i (i<4), 16B unit u ----
    int kp0 = tid >> 4, u = tid & 15;
    uint32_t bD0 = (uint32_t)kp0 * SM_B_STRIDE + (uint32_t)u * 16u;
    const unsigned* Brow = B + (size_t)e * estrideU + (size_t)kp0 * N + n0 + u * 4;

    // ---- A fragment addressing (ldmatrix lanes) ----
    int rowLane = (lane & 7) + ((lane >> 3) & 1) * 8;
    int khalf = lane >> 4;
    uint32_t aRelL = (uint32_t)(wm * 64 + rowLane) * 128u;
    uint32_t uoffL[4];
#pragma unroll
    for (int ks = 0; ks < 4; ks++)
        uoffL[ks] = 16u * (uint32_t)((2 * ks + khalf) ^ (rowLane & 7));

    // ---- B fragment addressing ----
    uint32_t brel[4];
#pragma unroll
    for (int nt = 0; nt < 4; nt++)
        brel[nt] = (uint32_t)tig * SM_B_STRIDE +
                   (uint32_t)(wn * 32 + nt * 8 + gid) * 4u;

    float c[4][4][4];
#pragma unroll
    for (int mt = 0; mt < 4; mt++)
#pragma unroll
        for (int nt = 0; nt < 4; nt++)
#pragma unroll
            for (int q = 0; q < 4; q++) c[mt][nt][q] = 0.f;

    const int nk = Ksize / 64;

    // prologue: stages 0, 1
#pragma unroll
    for (int s = 0; s < 2; s++) {
        uint32_t sb = sm + (uint32_t)s * STAGE_BYTES;
#pragma unroll
        for (int i = 0; i < 8; i++)
            cp16(sb + aD0 + (uint32_t)i * 2048u, Ab + arow[i] + s * 64);
#pragma unroll
        for (int i = 0; i < 4; i++)
            cp16(sb + SM_A_BYTES + bD0 + (uint32_t)i * (8u * SM_B_STRIDE),
                 Brow + (size_t)(s * 32 + 8 * i) * N);
        cp_commit();
    }

    int stage = 0;
    for (int kc = 0; kc < nk; kc++) {
        cp_wait1();
        __syncthreads();
        if (kc + 2 < nk) {
            int s2 = stage + 2; if (s2 >= NSTAGE) s2 -= NSTAGE;
            uint32_t sb = sm + (uint32_t)s2 * STAGE_BYTES;
            int ko = (kc + 2) * 64;
#pragma unroll
            for (int i = 0; i < 8; i++)
                cp16(sb + aD0 + (uint32_t)i * 2048u, Ab + arow[i] + ko);
#pragma unroll
            for (int i = 0; i < 4; i++)
                cp16(sb + SM_A_BYTES + bD0 + (uint32_t)i * (8u * SM_B_STRIDE),
                     Brow + (size_t)((kc + 2) * 32 + 8 * i) * N);
        }
        cp_commit();

        uint32_t aB = sm + (uint32_t)stage * STAGE_BYTES;
        uint32_t bB = aB + SM_A_BYTES;
#pragma unroll
        for (int ks = 0; ks < 4; ks++) {
            uint32_t af[4][4];
#pragma unroll
            for (int mt = 0; mt < 4; mt++)
                ldm4(aB + aRelL + (uint32_t)(mt * 2048) + uoffL[ks], af[mt]);
            uint32_t bf[4][2];
#pragma unroll
            for (int nt = 0; nt < 4; nt++) {
                uint32_t b0 = bB + brel[nt] + (uint32_t)(ks * 8 * SM_B_STRIDE);
                bf[nt][0] = ldsu(b0);
                bf[nt][1] = ldsu(b0 + 4u * SM_B_STRIDE);
            }
#pragma unroll
            for (int mt = 0; mt < 4; mt++)
#pragma unroll
                for (int nt = 0; nt < 4; nt++)
                    mma_f16(c[mt][nt], af[mt], bf[nt]);
        }
        stage++; if (stage >= NSTAGE) stage -= NSTAGE;
    }

    // ---- epilogue: +bias (, relu); RELU path stores fp16 h, else fp32 y ----
#pragma unroll
    for (int mt = 0; mt < 4; mt++) {
#pragma unroll
        for (int half = 0; half < 2; half++) {
            int r = wm * 64 + mt * 16 + gid + half * 8;
            if (r < mc) {
#pragma unroll
                for (int nt = 0; nt < 4; nt++) {
                    int nc = n0 + wn * 32 + nt * 8 + 2 * tig;
                    float v0 = c[mt][nt][half * 2 + 0] + biasE[nc];
                    float v1 = c[mt][nt][half * 2 + 1] + biasE[nc + 1];
                    if (RELU) {
                        v0 = fmaxf(v0, 0.f); v1 = fmaxf(v1, 0.f);
                        unsigned* orow = reinterpret_cast<unsigned*>(
                            g_hh + (size_t)(slot0 + r) * N);
                        orow[nc / 2] = pack2(v0, v1);
                    } else {
                        float* orow = g_y + (size_t)(slot0 + r) * N;
                        orow[nc]     = v0;
                        orow[nc + 1] = v1;
                    }
                }
            }
        }
    }
}

// ---------------- combine ----------------
__global__ void combine_kernel(float* __restrict__ out) {
    int idx = blockIdx.x * blockDim.x + threadIdx.x;
    if (idx >= T_TOK * (DMODEL / 4)) return;
    int t = idx / (DMODEL / 4);
    int j = (idx % (DMODEL / 4)) * 4;
    float w0 = g_w0[t], w1 = g_w1w[t];
    const float4 a = *reinterpret_cast<const float4*>(&g_y[(size_t)g_s0[t] * DMODEL + j]);
    const float4 b = *reinterpret_cast<const float4*>(&g_y[(size_t)g_s1[t] * DMODEL + j]);
    float4 o;
    o.x = w0 * a.x + w1 * b.x;
    o.y = w0 * a.y + w1 * b.y;
    o.z = w0 * a.z + w1 * b.z;
    o.w = w0 * a.w + w1 * b.w;
    *reinterpret_cast<float4*>(out + (size_t)t * DMODEL + j) = o;
}

// ---------------- launch (index 3 = GEMM1 for ncu) ----------------
extern "C" void kernel_launch(void* const* d_in, const int* in_sizes, int n_in,
                              void* d_out, int out_size) {
    const float* x      = (const float*)d_in[0];
    const float* gumbel = (const float*)d_in[1];
    const float* gw     = (const float*)d_in[2];
    const float* gb     = (const float*)d_in[3];
    const float* w1     = (const float*)d_in[4];
    const float* b1     = (const float*)d_in[5];
    const float* w2     = (const float*)d_in[6];
    const float* b2     = (const float*)d_in[7];
    float* out = (float*)d_out;

    cudaFuncSetAttribute(gemm_fp16<true, true>,
                         cudaFuncAttributeMaxDynamicSharedMemorySize, SMEM_TOT);
    cudaFuncSetAttribute(gemm_fp16<false, false>,
                         cudaFuncAttributeMaxDynamicSharedMemorySize, SMEM_TOT);

    __half* xh;  cudaGetSymbolAddress((void**)&xh,  g_xh);
    unsigned* w1h; cudaGetSymbolAddress((void**)&w1h, g_w1h);
    unsigned* w2h; cudaGetSymbolAddress((void**)&w2h, g_w2h);

    // 0: weight conversion to packed half2 (+ counter zeroing)
    size_t nU = 2 * W_UINTS;
    convert_w<<<(unsigned)((nU + 255) / 256), 256>>>(w1, w2);
    // 1: gate
    gate_kernel<<<T_TOK * 32 / 256, 256>>>(x, gumbel, gw, gb);
    // 2: tile map
    tilemap_kernel<<<1, 32>>>();
    // 3: GEMM1  h = fp16(relu(xh[tok] @ w1[e] + b1[e]))   K=DMODEL, N=DFF
    gemm_fp16<true, true><<<dim3(DFF / 64, MAXTILES), 128, SMEM_TOT>>>(
        xh, DMODEL, w1h, (long)(DMODEL / 2) * DFF, DFF, b1, DMODEL);
    // 4: GEMM2  y = hh @ w2[e] + b2[e]                    K=DFF, N=DMODEL
    gemm_fp16<false, false><<<dim3(DMODEL / 64, MAXTILES), 128, SMEM_TOT>>>(
        nullptr, DFF, w2h, (long)(DFF / 2) * DMODEL, DMODEL, b2, DFF);
    // 5: combine
    combine_kernel<<<(T_TOK * (DMODEL / 4) + 255) / 256, 256>>>(out);
}

// round 14
// speedup vs baseline: 1.0020x; 1.0020x over previous
#include <cuda_runtime.h>
#include <cuda_fp16.h>
#include <cstdint>

// ---------------- problem constants ----------------
#define T_TOK   8192
#define DMODEL  1024
#define DFF     4096
#define NEXP    8
#define ECAP    4096
#define NSLOTS  (NEXP * ECAP)                  // 32768
#define MAXTILES 160

// ---------------- device scratch (static; no allocation) ----------------
__device__ __align__(16) __half    g_hh[(size_t)NSLOTS * DFF];        // 256 MiB h (fp16)
__device__ __align__(16) float     g_y[(size_t)NSLOTS * DMODEL];      // 128 MiB
__device__ __align__(16) __half    g_xh[(size_t)T_TOK * DMODEL];      // 16 MiB
// packed half2 weights: [e][kp][n], uint = (half lo = k=2kp, half hi = k=2kp+1)
__device__ __align__(16) unsigned  g_w1h[(size_t)NEXP * (DMODEL / 2) * DFF];  // 64 MiB
__device__ __align__(16) unsigned  g_w2h[(size_t)NEXP * (DFF / 2) * DMODEL];  // 64 MiB
__device__ int   g_tok[NSLOTS];
__device__ int   g_s0[T_TOK], g_s1[T_TOK];
__device__ float g_w0[T_TOK], g_w1w[T_TOK];
__device__ int   g_fill[NEXP];                 // static-zero init; tilemap resets after use
__device__ int   g_ntiles;
__device__ int   g_tile_e[MAXTILES], g_tile_start[MAXTILES], g_tile_cnt[MAXTILES];

// ---------------- helpers ----------------
__device__ __forceinline__ uint32_t smem_u32(const void* p) {
    uint32_t a;
    asm("{ .reg .u64 t; cvta.to.shared.u64 t, %1; cvt.u32.u64 %0, t; }" : "=r"(a) : "l"(p));
    return a;
}
__device__ __forceinline__ void cp16(uint32_t dst, const void* src) {
    asm volatile("cp.async.cg.shared.global [%0], [%1], 16;" :: "r"(dst), "l"(src));
}
__device__ __forceinline__ void cp_commit() {
    asm volatile("cp.async.commit_group;" ::: "memory");
}
__device__ __forceinline__ void cp_wait1() {
    asm volatile("cp.async.wait_group 1;" ::: "memory");
}
__device__ __forceinline__ void pfL2(const void* p) {
    asm volatile("prefetch.global.L2 [%0];" :: "l"(p));
}
__device__ __forceinline__ uint32_t ldsu(uint32_t addr) {
    uint32_t v;
    asm volatile("ld.shared.b32 %0, [%1];" : "=r"(v) : "r"(addr));
    return v;
}
__device__ __forceinline__ void ldm4(uint32_t addr, uint32_t* r) {
    asm volatile("ldmatrix.sync.aligned.m8n8.x4.shared.b16 {%0,%1,%2,%3}, [%4];"
        : "=r"(r[0]), "=r"(r[1]), "=r"(r[2]), "=r"(r[3]) : "r"(addr));
}
__device__ __forceinline__ unsigned pack2(float lo, float hi) {
    __half2 h = __floats2half2_rn(lo, hi);
    return *reinterpret_cast<unsigned*>(&h);
}
__device__ __forceinline__ void mma_f16(float* d, const uint32_t* a, const uint32_t* b) {
    asm volatile(
        "mma.sync.aligned.m16n8k16.row.col.f32.f16.f16.f32 "
        "{%0,%1,%2,%3}, {%4,%5,%6,%7}, {%8,%9}, {%0,%1,%2,%3};\n"
        : "+f"(d[0]), "+f"(d[1]), "+f"(d[2]), "+f"(d[3])
        : "r"(a[0]), "r"(a[1]), "r"(a[2]), "r"(a[3]),
          "r"(b[0]), "r"(b[1]));
}

// ---- launch 0: FUSED weight conversion + gate (independent work, block split) ----
#define W_UINTS ((size_t)NEXP * (DMODEL / 2) * DFF)         // 16,777,216
#define CONV_BLOCKS ((unsigned)((2 * W_UINTS) / 256))        // 131072
#define GATE_BLOCKS (T_TOK * 32 / 256)                       // 1024

__global__ void fused_prep(const float* __restrict__ w1, const float* __restrict__ w2,
                           const float* __restrict__ x, const float* __restrict__ gumbel,
                           const float* __restrict__ gw, const float* __restrict__ gb) {
    if (blockIdx.x < CONV_BLOCKS) {
        size_t i = (size_t)blockIdx.x * 256 + threadIdx.x;
        if (i < W_UINTS) {
            size_t row = i / DFF, n = i % DFF;
            size_t e = row / (DMODEL / 2), kp = row % (DMODEL / 2);
            size_t base = (e * DMODEL + 2 * kp) * DFF + n;
            g_w1h[i] = pack2(w1[base], w1[base + DFF]);
        } else {
            size_t j = i - W_UINTS;
            size_t row = j / DMODEL, n = j % DMODEL;
            size_t e = row / (DFF / 2), kp = row % (DFF / 2);
            size_t base = (e * DFF + 2 * kp) * DMODEL + n;
            g_w2h[j] = pack2(w2[base], w2[base + DMODEL]);
        }
        return;
    }
    // ---- gate part ----
    int blk = blockIdx.x - CONV_BLOCKS;
    int t = (blk * 256 + threadIdx.x) >> 5;
    int lane = threadIdx.x & 31;
    if (t >= T_TOK) return;
    const float* xr = x + (size_t)t * DMODEL;
    unsigned* xo = reinterpret_cast<unsigned*>(g_xh + (size_t)t * DMODEL);
    float acc[NEXP];
#pragma unroll
    for (int e = 0; e < NEXP; e++) acc[e] = 0.f;
    for (int d = lane * 4; d < DMODEL; d += 128) {
        float4 xv = *reinterpret_cast<const float4*>(xr + d);
        uint2 hv;
        hv.x = pack2(xv.x, xv.y);
        hv.y = pack2(xv.z, xv.w);
        *reinterpret_cast<uint2*>(xo + d / 2) = hv;
        float xs[4] = {xv.x, xv.y, xv.z, xv.w};
        const float* g0 = gw + (size_t)d * NEXP;
#pragma unroll
        for (int j = 0; j < 4; j++)
#pragma unroll
            for (int e = 0; e < NEXP; e++) acc[e] += xs[j] * g0[j * NEXP + e];
    }
#pragma unroll
    for (int e = 0; e < NEXP; e++)
#pragma unroll
        for (int off = 16; off; off >>= 1)
            acc[e] += __shfl_xor_sync(0xffffffffu, acc[e], off);
    if (lane == 0) {
        float v[NEXP];
#pragma unroll
        for (int e = 0; e < NEXP; e++) v[e] = acc[e] + gb[e] + gumbel[t * NEXP + e];
        int b0 = 0; float m0 = v[0];
#pragma unroll
        for (int e = 1; e < NEXP; e++) if (v[e] > m0) { m0 = v[e]; b0 = e; }
        int b1 = -1; float m1 = -3.4e38f;
#pragma unroll
        for (int e = 0; e < NEXP; e++) {
            if (e == b0) continue;
            if (v[e] > m1) { m1 = v[e]; b1 = e; }
        }
        float e1v = expf(m1 - m0);
        float inv = 1.f / (1.f + e1v);
        g_w0[t] = inv; g_w1w[t] = e1v * inv;
        int s0 = b0 * ECAP + atomicAdd(&g_fill[b0], 1);
        g_tok[s0] = t; g_s0[t] = s0;
        int s1 = b1 * ECAP + atomicAdd(&g_fill[b1], 1);
        g_tok[s1] = t; g_s1[t] = s1;
    }
}

// ---- launch 1: build m-tile map, then reset g_fill for next graph replay ----
__global__ void tilemap_kernel() {
    if (threadIdx.x == 0) {
        int nt = 0;
        for (int e = 0; e < NEXP; e++) {
            int c = g_fill[e];
            if (c > ECAP) c = ECAP;
            int base = e * ECAP;
            for (int s = 0; s < c; s += 128) {
                g_tile_e[nt] = e;
                g_tile_start[nt] = base + s;
                g_tile_cnt[nt] = (c - s < 128) ? (c - s) : 128;
                nt++;
            }
            g_fill[e] = 0;   // reset for next replay (initial state is static zero)
        }
        g_ntiles = nt;
    }
}

// ---------------- grouped GEMM, fp16 m16n8k16, ldmatrix A fragments ----------------
// BM=128 BN=128 BK=64(half), 4 warps (warp tile 64x64), cp.async 3-stage.
// A stage: 128 rows x 128B, unit swizzle g^(r&7)  -> conflict-free (ldmatrix too).
// B stage: 32 kp-rows x 544B                       -> conflict-free scalar LDS.
// A rows L2-prefetched 4 chunks ahead (covers DRAM-resident A in GEMM2).
#define SM_A_BYTES 16384
#define SM_B_STRIDE 544
#define STAGE_BYTES (SM_A_BYTES + 32 * SM_B_STRIDE)   // 33792
#define NSTAGE 3
#define SM_TOKS (NSTAGE * STAGE_BYTES)                 // 101376
#define SMEM_TOT (SM_TOKS + 512)

template <bool GATHER, bool RELU>
__global__ void __launch_bounds__(128, 2)
gemm_fp16(const __half* __restrict__ Aext, int lda,
          const unsigned* __restrict__ B, long estrideU, int N,
          const float* __restrict__ bias, int Ksize) {
    extern __shared__ char smem[];
    int tix = blockIdx.y;
    if (tix >= g_ntiles) return;
    int e = g_tile_e[tix];
    int slot0 = g_tile_start[tix];
    int mc = g_tile_cnt[tix];
    int n0 = blockIdx.x * 128;

    uint32_t sm = smem_u32(smem);
    int tid = threadIdx.x;
    int lane = tid & 31, wid = tid >> 5;
    int wm = wid >> 1, wn = wid & 1;
    int gid = lane >> 2, tig = lane & 3;

    const __half* Abase = GATHER ? Aext : g_hh;
    const float* biasE = bias + (size_t)e * N;

    int* toks = reinterpret_cast<int*>(smem + SM_TOKS);
    if (GATHER) {
        if (tid < 128) {
            int r = tid < mc ? tid : (mc - 1);
            toks[tid] = g_tok[slot0 + r];
        }
        __syncthreads();
    }

    // ---- A staging map ----
    int r0 = tid >> 3, kg = tid & 7;
    uint32_t aD0 = (uint32_t)r0 * 128u + 16u * (uint32_t)(kg ^ (r0 & 7));
    uint32_t arow[8];
#pragma unroll
    for (int i = 0; i < 8; i++) {
        int row = i * 16 + r0;
        int rr = GATHER ? toks[row] : (slot0 + row);
        arow[i] = (uint32_t)rr * (uint32_t)lda;   // in halves
    }
    const __half* Ab = Abase + kg * 8;

    // ---- B staging map ----
    int kpL = tid >> 5, ucol = tid & 31;
    uint32_t bD0 = (uint32_t)kpL * SM_B_STRIDE + (uint32_t)ucol * 16u;
    const unsigned* Brow = B + (size_t)e * estrideU + (size_t)kpL * N + n0 + ucol * 4;

    // ---- A fragment addressing (ldmatrix per-lane rows) ----
    int rowLane = (lane & 7) + ((lane >> 3) & 1) * 8;
    int khalf = lane >> 4;
    uint32_t aRelL = (uint32_t)(wm * 64 + rowLane) * 128u;
    uint32_t uoffL[4];
#pragma unroll
    for (int ks = 0; ks < 4; ks++)
        uoffL[ks] = 16u * (uint32_t)((2 * ks + khalf) ^ (rowLane & 7));

    // ---- B fragment addressing ----
    uint32_t brel[8];
#pragma unroll
    for (int nt = 0; nt < 8; nt++)
        brel[nt] = (uint32_t)tig * SM_B_STRIDE +
                   (uint32_t)(wn * 64 + nt * 8 + gid) * 4u;

    float c[4][8][4];
#pragma unroll
    for (int mt = 0; mt < 4; mt++)
#pragma unroll
        for (int nt = 0; nt < 8; nt++)
#pragma unroll
            for (int q = 0; q < 4; q++) c[mt][nt][q] = 0.f;

    const int nk = Ksize / 64;

    // prologue: stages 0, 1 + L2 prefetch of chunks 2..3 A rows
#pragma unroll
    for (int s = 0; s < 2; s++) {
        uint32_t sb = sm + (uint32_t)s * STAGE_BYTES;
#pragma unroll
        for (int i = 0; i < 8; i++)
            cp16(sb + aD0 + (uint32_t)i * 2048u, Ab + arow[i] + s * 64);
#pragma unroll
        for (int i = 0; i < 8; i++)
            cp16(sb + SM_A_BYTES + bD0 + (uint32_t)i * (4u * SM_B_STRIDE),
                 Brow + (size_t)(s * 32 + 4 * i) * N);
        cp_commit();
    }
    if (kg == 0) {
#pragma unroll
        for (int s = 2; s < 4; s++) {
            if (s < nk) {
#pragma unroll
                for (int i = 0; i < 8; i++)
                    pfL2(Abase + arow[i] + s * 64);
            }
        }
    }

    int stage = 0;
    for (int kc = 0; kc < nk; kc++) {
        cp_wait1();
        __syncthreads();
        if (kc + 2 < nk) {
            int s2 = stage + 2; if (s2 >= NSTAGE) s2 -= NSTAGE;
            uint32_t sb = sm + (uint32_t)s2 * STAGE_BYTES;
            int ko = (kc + 2) * 64;
#pragma unroll
            for (int i = 0; i < 8; i++)
                cp16(sb + aD0 + (uint32_t)i * 2048u, Ab + arow[i] + ko);
#pragma unroll
            for (int i = 0; i < 8; i++)
                cp16(sb + SM_A_BYTES + bD0 + (uint32_t)i * (4u * SM_B_STRIDE),
                     Brow + (size_t)((kc + 2) * 32 + 4 * i) * N);
        }
        cp_commit();
        // L2 prefetch of A rows 4 chunks ahead (one lane-group per 128B line)
        if (kg == 0 && kc + 4 < nk) {
            int kp4 = (kc + 4) * 64;
#pragma unroll
            for (int i = 0; i < 8; i++)
                pfL2(Abase + arow[i] + kp4);
        }

        uint32_t aB = sm + (uint32_t)stage * STAGE_BYTES;
        uint32_t bB = aB + SM_A_BYTES;
#pragma unroll
        for (int ks = 0; ks < 4; ks++) {
            uint32_t af[4][4];
#pragma unroll
            for (int mt = 0; mt < 4; mt++)
                ldm4(aB + aRelL + (uint32_t)(mt * 2048) + uoffL[ks], af[mt]);
            uint32_t bf[8][2];
#pragma unroll
            for (int nt = 0; nt < 8; nt++) {
                uint32_t b0 = bB + brel[nt] + (uint32_t)(ks * 8 * SM_B_STRIDE);
                bf[nt][0] = ldsu(b0);
                bf[nt][1] = ldsu(b0 + 4u * SM_B_STRIDE);
            }
#pragma unroll
            for (int mt = 0; mt < 4; mt++)
#pragma unroll
                for (int nt = 0; nt < 8; nt++)
                    mma_f16(c[mt][nt], af[mt], bf[nt]);
        }
        stage++; if (stage >= NSTAGE) stage -= NSTAGE;
    }

    // ---- epilogue: +bias (, relu); RELU path stores fp16 h, else fp32 y ----
#pragma unroll
    for (int mt = 0; mt < 4; mt++) {
#pragma unroll
        for (int half = 0; half < 2; half++) {
            int r = wm * 64 + mt * 16 + gid + half * 8;
            if (r < mc) {
#pragma unroll
                for (int nt = 0; nt < 8; nt++) {
                    int nc = n0 + wn * 64 + nt * 8 + 2 * tig;
                    float v0 = c[mt][nt][half * 2 + 0] + biasE[nc];
                    float v1 = c[mt][nt][half * 2 + 1] + biasE[nc + 1];
                    if (RELU) {
                        v0 = fmaxf(v0, 0.f); v1 = fmaxf(v1, 0.f);
                        unsigned* orow = reinterpret_cast<unsigned*>(
                            g_hh + (size_t)(slot0 + r) * N);
                        orow[nc / 2] = pack2(v0, v1);
                    } else {
                        float* orow = g_y + (size_t)(slot0 + r) * N;
                        orow[nc]     = v0;
                        orow[nc + 1] = v1;
                    }
                }
            }
        }
    }
}

// ---------------- combine ----------------
__global__ void combine_kernel(float* __restrict__ out) {
    int idx = blockIdx.x * blockDim.x + threadIdx.x;
    if (idx >= T_TOK * (DMODEL / 4)) return;
    int t = idx / (DMODEL / 4);
    int j = (idx % (DMODEL / 4)) * 4;
    float w0 = g_w0[t], w1 = g_w1w[t];
    const float4 a = *reinterpret_cast<const float4*>(&g_y[(size_t)g_s0[t] * DMODEL + j]);
    const float4 b = *reinterpret_cast<const float4*>(&g_y[(size_t)g_s1[t] * DMODEL + j]);
    float4 o;
    o.x = w0 * a.x + w1 * b.x;
    o.y = w0 * a.y + w1 * b.y;
    o.z = w0 * a.z + w1 * b.z;
    o.w = w0 * a.w + w1 * b.w;
    *reinterpret_cast<float4*>(out + (size_t)t * DMODEL + j) = o;
}

// ---------------- launch (index 3 = GEMM2 for ncu this round) ----------------
extern "C" void kernel_launch(void* const* d_in, const int* in_sizes, int n_in,
                              void* d_out, int out_size) {
    const float* x      = (const float*)d_in[0];
    const float* gumbel = (const float*)d_in[1];
    const float* gw     = (const float*)d_in[2];
    const float* gb     = (const float*)d_in[3];
    const float* w1     = (const float*)d_in[4];
    const float* b1     = (const float*)d_in[5];
    const float* w2     = (const float*)d_in[6];
    const float* b2     = (const float*)d_in[7];
    float* out = (float*)d_out;

    cudaFuncSetAttribute(gemm_fp16<true, true>,
                         cudaFuncAttributeMaxDynamicSharedMemorySize, SMEM_TOT);
    cudaFuncSetAttribute(gemm_fp16<false, false>,
                         cudaFuncAttributeMaxDynamicSharedMemorySize, SMEM_TOT);

    __half* xh;  cudaGetSymbolAddress((void**)&xh,  g_xh);
    unsigned* w1h; cudaGetSymbolAddress((void**)&w1h, g_w1h);
    unsigned* w2h; cudaGetSymbolAddress((void**)&w2h, g_w2h);

    // 0: fused weight conversion + gate (g_fill is zero: static init / tilemap reset)
    fused_prep<<<CONV_BLOCKS + GATE_BLOCKS, 256>>>(w1, w2, x, gumbel, gw, gb);
    // 1: tile map (+ g_fill reset for next replay)
    tilemap_kernel<<<1, 32>>>();
    // 2: GEMM1  h = fp16(relu(xh[tok] @ w1[e] + b1[e]))   K=DMODEL, N=DFF
    gemm_fp16<true, true><<<dim3(DFF / 128, MAXTILES), 128, SMEM_TOT>>>(
        xh, DMODEL, w1h, (long)(DMODEL / 2) * DFF, DFF, b1, DMODEL);
    // 3: GEMM2  y = hh @ w2[e] + b2[e]                    K=DFF, N=DMODEL  <- ncu
    gemm_fp16<false, false><<<dim3(DMODEL / 128, MAXTILES), 128, SMEM_TOT>>>(
        nullptr, DFF, w2h, (long)(DFF / 2) * DMODEL, DMODEL, b2, DFF);
    // 4: combine
    combine_kernel<<<(T_TOK * (DMODEL / 4) + 255) / 256, 256>>>(out);
}

// round 16
// speedup vs baseline: 1.1060x; 1.1038x over previous
#include <cuda_runtime.h>
#include <cuda_fp16.h>
#include <cstdint>

// ---------------- problem constants ----------------
#define T_TOK   8192
#define DMODEL  1024
#define DFF     4096
#define NEXP    8
#define ECAP    4096
#define NSLOTS  (NEXP * ECAP)                  // 32768
#define MAXTILES 160

// ---------------- device scratch (static; no allocation) ----------------
__device__ __align__(16) __half    g_hh[(size_t)NSLOTS * DFF];        // 256 MiB h (fp16)
__device__ __align__(16) float     g_y[(size_t)NSLOTS * DMODEL];      // 128 MiB
__device__ __align__(16) __half    g_xh[(size_t)T_TOK * DMODEL];      // 16 MiB
// packed half2 weights: [e][kp][n], uint = (half lo = k=2kp, half hi = k=2kp+1)
__device__ __align__(16) unsigned  g_w1h[(size_t)NEXP * (DMODEL / 2) * DFF];  // 64 MiB
__device__ __align__(16) unsigned  g_w2h[(size_t)NEXP * (DFF / 2) * DMODEL];  // 64 MiB
__device__ int   g_tok[NSLOTS];
__device__ int   g_s0[T_TOK], g_s1[T_TOK];
__device__ float g_w0[T_TOK], g_w1w[T_TOK];
__device__ int   g_fill[NEXP];
__device__ int   g_ntiles;
__device__ int   g_tile_e[MAXTILES], g_tile_start[MAXTILES], g_tile_cnt[MAXTILES];

// ---------------- helpers ----------------
__device__ __forceinline__ uint32_t smem_u32(const void* p) {
    uint32_t a;
    asm("{ .reg .u64 t; cvta.to.shared.u64 t, %1; cvt.u32.u64 %0, t; }" : "=r"(a) : "l"(p));
    return a;
}
__device__ __forceinline__ void cp16(uint32_t dst, const void* src) {
    asm volatile("cp.async.cg.shared.global [%0], [%1], 16;" :: "r"(dst), "l"(src));
}
__device__ __forceinline__ void cp_commit() {
    asm volatile("cp.async.commit_group;" ::: "memory");
}
__device__ __forceinline__ void cp_wait1() {
    asm volatile("cp.async.wait_group 1;" ::: "memory");
}
__device__ __forceinline__ uint32_t ldsu(uint32_t addr) {
    uint32_t v;
    asm volatile("ld.shared.b32 %0, [%1];" : "=r"(v) : "r"(addr));
    return v;
}
__device__ __forceinline__ void ldm4(uint32_t addr, uint32_t* r) {
    asm volatile("ldmatrix.sync.aligned.m8n8.x4.shared.b16 {%0,%1,%2,%3}, [%4];"
        : "=r"(r[0]), "=r"(r[1]), "=r"(r[2]), "=r"(r[3]) : "r"(addr));
}
__device__ __forceinline__ unsigned pack2(float lo, float hi) {
    __half2 h = __floats2half2_rn(lo, hi);
    return *reinterpret_cast<unsigned*>(&h);
}
__device__ __forceinline__ void mma_f16(float* d, const uint32_t* a, const uint32_t* b) {
    asm volatile(
        "mma.sync.aligned.m16n8k16.row.col.f32.f16.f16.f32 "
        "{%0,%1,%2,%3}, {%4,%5,%6,%7}, {%8,%9}, {%0,%1,%2,%3};\n"
        : "+f"(d[0]), "+f"(d[1]), "+f"(d[2]), "+f"(d[3])
        : "r"(a[0]), "r"(a[1]), "r"(a[2]), "r"(a[3]),
          "r"(b[0]), "r"(b[1]));
}

// ---- dummy no-op kernels (shift convert_w to profiled launch index 3) ----
__global__ void dummy_kernel() {}

// ---- convert w1/w2 -> k-pair-interleaved half2, vectorized x4 (+ zero counters) ----
#define W_UINTS  ((size_t)NEXP * (DMODEL / 2) * DFF)    // 16,777,216 per tensor
#define W_VEC4   (W_UINTS / 4)                          // uint4 stores per tensor
__global__ void convert_w(const float* __restrict__ w1, const float* __restrict__ w2) {
    if (blockIdx.x == 0 && threadIdx.x < NEXP) g_fill[threadIdx.x] = 0;
    size_t i4 = (size_t)blockIdx.x * blockDim.x + threadIdx.x;
    if (i4 < W_VEC4) {
        size_t i = i4 * 4;                       // first uint index
        size_t row = i / DFF, n = i % DFF;       // row = e*(K/2)+kp, n multiple of 4
        size_t e = row / (DMODEL / 2), kp = row % (DMODEL / 2);
        size_t base = (e * DMODEL + 2 * kp) * DFF + n;
        float4 f0 = *reinterpret_cast<const float4*>(w1 + base);        // k = 2kp
        float4 f1 = *reinterpret_cast<const float4*>(w1 + base + DFF);  // k = 2kp+1
        uint4 o;
        o.x = pack2(f0.x, f1.x); o.y = pack2(f0.y, f1.y);
        o.z = pack2(f0.z, f1.z); o.w = pack2(f0.w, f1.w);
        *reinterpret_cast<uint4*>(g_w1h + i) = o;
    } else if (i4 < 2 * W_VEC4) {
        size_t i = (i4 - W_VEC4) * 4;
        size_t row = i / DMODEL, n = i % DMODEL;
        size_t e = row / (DFF / 2), kp = row % (DFF / 2);
        size_t base = (e * DFF + 2 * kp) * DMODEL + n;
        float4 f0 = *reinterpret_cast<const float4*>(w2 + base);
        float4 f1 = *reinterpret_cast<const float4*>(w2 + base + DMODEL);
        uint4 o;
        o.x = pack2(f0.x, f1.x); o.y = pack2(f0.y, f1.y);
        o.z = pack2(f0.z, f1.z); o.w = pack2(f0.w, f1.w);
        *reinterpret_cast<uint4*>(g_w2h + i) = o;
    }
}

// ---- gate + fp16(x) + direct slot assignment ----
__global__ void gate_kernel(const float* __restrict__ x, const float* __restrict__ gumbel,
                            const float* __restrict__ gw, const float* __restrict__ gb) {
    int t = (blockIdx.x * blockDim.x + threadIdx.x) >> 5;
    int lane = threadIdx.x & 31;
    if (t >= T_TOK) return;
    const float* xr = x + (size_t)t * DMODEL;
    unsigned* xo = reinterpret_cast<unsigned*>(g_xh + (size_t)t * DMODEL);
    float acc[NEXP];
#pragma unroll
    for (int e = 0; e < NEXP; e++) acc[e] = 0.f;
    for (int d = lane * 4; d < DMODEL; d += 128) {
        float4 xv = *reinterpret_cast<const float4*>(xr + d);
        uint2 hv;
        hv.x = pack2(xv.x, xv.y);
        hv.y = pack2(xv.z, xv.w);
        *reinterpret_cast<uint2*>(xo + d / 2) = hv;
        float xs[4] = {xv.x, xv.y, xv.z, xv.w};
        const float* g0 = gw + (size_t)d * NEXP;
#pragma unroll
        for (int j = 0; j < 4; j++)
#pragma unroll
            for (int e = 0; e < NEXP; e++) acc[e] += xs[j] * g0[j * NEXP + e];
    }
#pragma unroll
    for (int e = 0; e < NEXP; e++)
#pragma unroll
        for (int off = 16; off; off >>= 1)
            acc[e] += __shfl_xor_sync(0xffffffffu, acc[e], off);
    if (lane == 0) {
        float v[NEXP];
#pragma unroll
        for (int e = 0; e < NEXP; e++) v[e] = acc[e] + gb[e] + gumbel[t * NEXP + e];
        int b0 = 0; float m0 = v[0];
#pragma unroll
        for (int e = 1; e < NEXP; e++) if (v[e] > m0) { m0 = v[e]; b0 = e; }
        int b1 = -1; float m1 = -3.4e38f;
#pragma unroll
        for (int e = 0; e < NEXP; e++) {
            if (e == b0) continue;
            if (v[e] > m1) { m1 = v[e]; b1 = e; }
        }
        float e1v = expf(m1 - m0);
        float inv = 1.f / (1.f + e1v);
        g_w0[t] = inv; g_w1w[t] = e1v * inv;
        int s0 = b0 * ECAP + atomicAdd(&g_fill[b0], 1);
        g_tok[s0] = t; g_s0[t] = s0;
        int s1 = b1 * ECAP + atomicAdd(&g_fill[b1], 1);
        g_tok[s1] = t; g_s1[t] = s1;
    }
}

// ---- build m-tile map, then reset g_fill for next graph replay ----
__global__ void tilemap_kernel() {
    if (threadIdx.x == 0) {
        int nt = 0;
        for (int e = 0; e < NEXP; e++) {
            int c = g_fill[e];
            if (c > ECAP) c = ECAP;
            int base = e * ECAP;
            for (int s = 0; s < c; s += 128) {
                g_tile_e[nt] = e;
                g_tile_start[nt] = base + s;
                g_tile_cnt[nt] = (c - s < 128) ? (c - s) : 128;
                nt++;
            }
            g_fill[e] = 0;   // reset for next replay (initial state is static zero)
        }
        g_ntiles = nt;
    }
}

// ---------------- grouped GEMM, fp16 m16n8k16, ldmatrix A fragments (R12 config) ---
// BM=128 BN=128 BK=64(half), 4 warps (warp tile 64x64), cp.async 3-stage.
#define SM_A_BYTES 16384
#define SM_B_STRIDE 544
#define STAGE_BYTES (SM_A_BYTES + 32 * SM_B_STRIDE)   // 33792
#define NSTAGE 3
#define SM_TOKS (NSTAGE * STAGE_BYTES)                 // 101376
#define SMEM_TOT (SM_TOKS + 512)

template <bool GATHER, bool RELU>
__global__ void __launch_bounds__(128, 2)
gemm_fp16(const __half* __restrict__ Aext, int lda,
          const unsigned* __restrict__ B, long estrideU, int N,
          const float* __restrict__ bias, int Ksize) {
    extern __shared__ char smem[];
    int tix = blockIdx.y;
    if (tix >= g_ntiles) return;
    int e = g_tile_e[tix];
    int slot0 = g_tile_start[tix];
    int mc = g_tile_cnt[tix];
    int n0 = blockIdx.x * 128;

    uint32_t sm = smem_u32(smem);
    int tid = threadIdx.x;
    int lane = tid & 31, wid = tid >> 5;
    int wm = wid >> 1, wn = wid & 1;
    int gid = lane >> 2, tig = lane & 3;

    const __half* Abase = GATHER ? Aext : g_hh;
    const float* biasE = bias + (size_t)e * N;

    int* toks = reinterpret_cast<int*>(smem + SM_TOKS);
    if (GATHER) {
        if (tid < 128) {
            int r = tid < mc ? tid : (mc - 1);
            toks[tid] = g_tok[slot0 + r];
        }
        __syncthreads();
    }

    // ---- A staging map ----
    int r0 = tid >> 3, kg = tid & 7;
    uint32_t aD0 = (uint32_t)r0 * 128u + 16u * (uint32_t)(kg ^ (r0 & 7));
    uint32_t arow[8];
#pragma unroll
    for (int i = 0; i < 8; i++) {
        int row = i * 16 + r0;
        int rr = GATHER ? toks[row] : (slot0 + row);
        arow[i] = (uint32_t)rr * (uint32_t)lda;   // in halves
    }
    const __half* Ab = Abase + kg * 8;

    // ---- B staging map ----
    int kpL = tid >> 5, ucol = tid & 31;
    uint32_t bD0 = (uint32_t)kpL * SM_B_STRIDE + (uint32_t)ucol * 16u;
    const unsigned* Brow = B + (size_t)e * estrideU + (size_t)kpL * N + n0 + ucol * 4;

    // ---- A fragment addressing (ldmatrix per-lane rows) ----
    int rowLane = (lane & 7) + ((lane >> 3) & 1) * 8;
    int khalf = lane >> 4;
    uint32_t aRelL = (uint32_t)(wm * 64 + rowLane) * 128u;
    uint32_t uoffL[4];
#pragma unroll
    for (int ks = 0; ks < 4; ks++)
        uoffL[ks] = 16u * (uint32_t)((2 * ks + khalf) ^ (rowLane & 7));

    // ---- B fragment addressing ----
    uint32_t brel[8];
#pragma unroll
    for (int nt = 0; nt < 8; nt++)
        brel[nt] = (uint32_t)tig * SM_B_STRIDE +
                   (uint32_t)(wn * 64 + nt * 8 + gid) * 4u;

    float c[4][8][4];
#pragma unroll
    for (int mt = 0; mt < 4; mt++)
#pragma unroll
        for (int nt = 0; nt < 8; nt++)
#pragma unroll
            for (int q = 0; q < 4; q++) c[mt][nt][q] = 0.f;

    const int nk = Ksize / 64;

    // prologue: stages 0, 1
#pragma unroll
    for (int s = 0; s < 2; s++) {
        uint32_t sb = sm + (uint32_t)s * STAGE_BYTES;
#pragma unroll
        for (int i = 0; i < 8; i++)
            cp16(sb + aD0 + (uint32_t)i * 2048u, Ab + arow[i] + s * 64);
#pragma unroll
        for (int i = 0; i < 8; i++)
            cp16(sb + SM_A_BYTES + bD0 + (uint32_t)i * (4u * SM_B_STRIDE),
                 Brow + (size_t)(s * 32 + 4 * i) * N);
        cp_commit();
    }

    int stage = 0;
    for (int kc = 0; kc < nk; kc++) {
        cp_wait1();
        __syncthreads();
        if (kc + 2 < nk) {
            int s2 = stage + 2; if (s2 >= NSTAGE) s2 -= NSTAGE;
            uint32_t sb = sm + (uint32_t)s2 * STAGE_BYTES;
            int ko = (kc + 2) * 64;
#pragma unroll
            for (int i = 0; i < 8; i++)
                cp16(sb + aD0 + (uint32_t)i * 2048u, Ab + arow[i] + ko);
#pragma unroll
            for (int i = 0; i < 8; i++)
                cp16(sb + SM_A_BYTES + bD0 + (uint32_t)i * (4u * SM_B_STRIDE),
                     Brow + (size_t)((kc + 2) * 32 + 4 * i) * N);
        }
        cp_commit();

        uint32_t aB = sm + (uint32_t)stage * STAGE_BYTES;
        uint32_t bB = aB + SM_A_BYTES;
#pragma unroll
        for (int ks = 0; ks < 4; ks++) {
            uint32_t af[4][4];
#pragma unroll
            for (int mt = 0; mt < 4; mt++)
                ldm4(aB + aRelL + (uint32_t)(mt * 2048) + uoffL[ks], af[mt]);
            uint32_t bf[8][2];
#pragma unroll
            for (int nt = 0; nt < 8; nt++) {
                uint32_t b0 = bB + brel[nt] + (uint32_t)(ks * 8 * SM_B_STRIDE);
                bf[nt][0] = ldsu(b0);
                bf[nt][1] = ldsu(b0 + 4u * SM_B_STRIDE);
            }
#pragma unroll
            for (int mt = 0; mt < 4; mt++)
#pragma unroll
                for (int nt = 0; nt < 8; nt++)
                    mma_f16(c[mt][nt], af[mt], bf[nt]);
        }
        stage++; if (stage >= NSTAGE) stage -= NSTAGE;
    }

    // ---- epilogue: +bias (, relu); RELU path stores fp16 h, else fp32 y ----
#pragma unroll
    for (int mt = 0; mt < 4; mt++) {
#pragma unroll
        for (int half = 0; half < 2; half++) {
            int r = wm * 64 + mt * 16 + gid + half * 8;
            if (r < mc) {
#pragma unroll
                for (int nt = 0; nt < 8; nt++) {
                    int nc = n0 + wn * 64 + nt * 8 + 2 * tig;
                    float v0 = c[mt][nt][half * 2 + 0] + biasE[nc];
                    float v1 = c[mt][nt][half * 2 + 1] + biasE[nc + 1];
                    if (RELU) {
                        v0 = fmaxf(v0, 0.f); v1 = fmaxf(v1, 0.f);
                        unsigned* orow = reinterpret_cast<unsigned*>(
                            g_hh + (size_t)(slot0 + r) * N);
                        orow[nc / 2] = pack2(v0, v1);
                    } else {
                        float* orow = g_y + (size_t)(slot0 + r) * N;
                        orow[nc]     = v0;
                        orow[nc + 1] = v1;
                    }
                }
            }
        }
    }
}

// ---------------- combine ----------------
__global__ void combine_kernel(float* __restrict__ out) {
    int idx = blockIdx.x * blockDim.x + threadIdx.x;
    if (idx >= T_TOK * (DMODEL / 4)) return;
    int t = idx / (DMODEL / 4);
    int j = (idx % (DMODEL / 4)) * 4;
    float w0 = g_w0[t], w1 = g_w1w[t];
    const float4 a = *reinterpret_cast<const float4*>(&g_y[(size_t)g_s0[t] * DMODEL + j]);
    const float4 b = *reinterpret_cast<const float4*>(&g_y[(size_t)g_s1[t] * DMODEL + j]);
    float4 o;
    o.x = w0 * a.x + w1 * b.x;
    o.y = w0 * a.y + w1 * b.y;
    o.z = w0 * a.z + w1 * b.z;
    o.w = w0 * a.w + w1 * b.w;
    *reinterpret_cast<float4*>(out + (size_t)t * DMODEL + j) = o;
}

// ---------------- launch (index 3 = convert_w gets the ncu capture) -------------
extern "C" void kernel_launch(void* const* d_in, const int* in_sizes, int n_in,
                              void* d_out, int out_size) {
    const float* x      = (const float*)d_in[0];
    const float* gumbel = (const float*)d_in[1];
    const float* gw     = (const float*)d_in[2];
    const float* gb     = (const float*)d_in[3];
    const float* w1     = (const float*)d_in[4];
    const float* b1     = (const float*)d_in[5];
    const float* w2     = (const float*)d_in[6];
    const float* b2     = (const float*)d_in[7];
    float* out = (float*)d_out;

    cudaFuncSetAttribute(gemm_fp16<true, true>,
                         cudaFuncAttributeMaxDynamicSharedMemorySize, SMEM_TOT);
    cudaFuncSetAttribute(gemm_fp16<false, false>,
                         cudaFuncAttributeMaxDynamicSharedMemorySize, SMEM_TOT);

    __half* xh;  cudaGetSymbolAddress((void**)&xh,  g_xh);
    unsigned* w1h; cudaGetSymbolAddress((void**)&w1h, g_w1h);
    unsigned* w2h; cudaGetSymbolAddress((void**)&w2h, g_w2h);

    // 0-2: no-op shims so the profiled launch index 3 lands on convert_w
    dummy_kernel<<<1, 32>>>();
    dummy_kernel<<<1, 32>>>();
    dummy_kernel<<<1, 32>>>();
    // 3: weight conversion (vectorized x4) + counter zeroing   <- ncu capture
    size_t nV = 2 * W_VEC4;
    convert_w<<<(unsigned)((nV + 255) / 256), 256>>>(w1, w2);
    // 4: gate
    gate_kernel<<<T_TOK * 32 / 256, 256>>>(x, gumbel, gw, gb);
    // 5: tile map (+ g_fill reset for next replay)
    tilemap_kernel<<<1, 32>>>();
    // 6: GEMM1  h = fp16(relu(xh[tok] @ w1[e] + b1[e]))   K=DMODEL, N=DFF
    gemm_fp16<true, true><<<dim3(DFF / 128, MAXTILES), 128, SMEM_TOT>>>(
        xh, DMODEL, w1h, (long)(DMODEL / 2) * DFF, DFF, b1, DMODEL);
    // 7: GEMM2  y = hh @ w2[e] + b2[e]                    K=DFF, N=DMODEL
    gemm_fp16<false, false><<<dim3(DMODEL / 128, MAXTILES), 128, SMEM_TOT>>>(
        nullptr, DFF, w2h, (long)(DFF / 2) * DMODEL, DMODEL, b2, DFF);
    // 8: combine
    combine_kernel<<<(T_TOK * (DMODEL / 4) + 255) / 256, 256>>>(out);
}